// round 6
// baseline (speedup 1.0000x reference)
#include <cuda_runtime.h>
#include <math.h>
#include <cstdint>

#define NNODES 20000
#define NEDGES 640000
#define NSZ 128
#define ESZ 20
#define CUTF 5.0f

// ---------------- device scratch ----------------
__device__ float g_so[NNODES * 384];
__device__ int g_hist[NNODES + 1];
__device__ int g_row[NNODES + 1];
__device__ int g_off[NNODES];
__device__ int g_dst[NEDGES];
__device__ int g_src[NEDGES];
__device__ float4 g_meta[NEDGES];        // (en0, en1, en2, cutoff)
__device__ float g_esr[NEDGES * ESZ];    // edge_state in CSR slot order

typedef unsigned long long u64;

// ---------------- helpers ----------------
__device__ __forceinline__ void fma2(u64& d, u64 a, u64 b) {
    asm("fma.rn.f32x2 %0, %1, %2, %0;" : "+l"(d) : "l"(a), "l"(b));
}
__device__ __forceinline__ u64 pack2(float x) {
    u64 r; asm("mov.b64 %0, {%1, %1};" : "=l"(r) : "f"(x)); return r;
}
__device__ __forceinline__ float2 unpack2(u64 a) {
    float2 f; asm("mov.b64 {%0, %1}, %2;" : "=f"(f.x), "=f"(f.y) : "l"(a));
    return f;
}
__device__ __forceinline__ float4 f4_mul(float4 a, float4 b) {
    return make_float4(a.x*b.x, a.y*b.y, a.z*b.z, a.w*b.w);
}
__device__ __forceinline__ float4 f4_msg(float4 xv, float4 g, float s, float4 f) {
    return make_float4(fmaf(xv.x, g.x, s*f.x), fmaf(xv.y, g.y, s*f.y),
                       fmaf(xv.z, g.z, s*f.z), fmaf(xv.w, g.w, s*f.w));
}
__device__ __forceinline__ void red4(float* p, float4 v) {
    asm volatile("red.global.add.v4.f32 [%0], {%1, %2, %3, %4};"
                 :: "l"(p), "f"(v.x), "f"(v.y), "f"(v.z), "f"(v.w) : "memory");
}

// ---------------------------------------------------------------------------
// CSR build (keyed by src) + edge pre-gather into CSR order
// ---------------------------------------------------------------------------
__global__ void csr_zero() {
    int i = blockIdx.x * 256 + threadIdx.x;
    if (i <= NNODES) g_hist[i] = 0;
}
__global__ void csr_hist(const int* __restrict__ edges) {
    int i = blockIdx.x * 256 + threadIdx.x;
    if (i < NEDGES) atomicAdd(&g_hist[edges[2 * i]], 1);
}
__global__ void __launch_bounds__(1024) csr_scan() {
    __shared__ int s[1024];
    const int t = threadIdx.x;
    const int C = 20;
    const int base = t * C;
    int sum = 0;
    #pragma unroll
    for (int j = 0; j < C; j++) {
        int idx = base + j;
        if (idx < NNODES) sum += g_hist[idx];
    }
    s[t] = sum;
    __syncthreads();
    for (int off = 1; off < 1024; off <<= 1) {
        int v = (t >= off) ? s[t - off] : 0;
        __syncthreads();
        s[t] += v;
        __syncthreads();
    }
    int run = s[t] - sum;
    #pragma unroll
    for (int j = 0; j < C; j++) {
        int idx = base + j;
        if (idx < NNODES) {
            g_row[idx] = run;
            g_off[idx] = run;
            run += g_hist[idx];
        }
    }
    if (t == 1023) g_row[NNODES] = NEDGES;
}
__global__ void csr_scatter(const int* __restrict__ edges,
                            const float* __restrict__ edge_vector,
                            const float* __restrict__ edge_distance,
                            const float4* __restrict__ edge_state4)
{
    int i = blockIdx.x * 256 + threadIdx.x;
    if (i >= NEDGES) return;
    const int s = edges[2 * i];
    const int d = edges[2 * i + 1];
    const int p = atomicAdd(&g_off[s], 1);
    g_dst[p] = d;
    g_src[p] = s;

    const float v0 = __ldg(&edge_vector[3 * i]);
    const float v1 = __ldg(&edge_vector[3 * i + 1]);
    const float v2 = __ldg(&edge_vector[3 * i + 2]);
    const float inv = 1.0f / fmaxf(sqrtf(v0*v0 + v1*v1 + v2*v2), 1e-12f);
    const float dist = __ldg(&edge_distance[i]);
    const float cu = (dist < CUTF)
        ? 0.5f * (__cosf(3.14159265358979f * dist * (1.0f / CUTF)) + 1.0f) : 0.0f;
    g_meta[p] = make_float4(v0 * inv, v1 * inv, v2 * inv, cu);

    float4* dst4 = (float4*)&g_esr[(size_t)p * ESZ];
    #pragma unroll
    for (int c = 0; c < 5; c++) dst4[c] = __ldg(&edge_state4[(size_t)i * 5 + c]);
}

// ---------------------------------------------------------------------------
// node MLP (f32x2) + init-out fold
// ---------------------------------------------------------------------------
#define NB 64

__global__ void __launch_bounds__(256) node_mlp(
    const float4* __restrict__ nss4, const float4* __restrict__ nsv4,
    const float* __restrict__ W1, const float* __restrict__ b1,
    const float* __restrict__ W2, const float* __restrict__ b2,
    float4* __restrict__ out)
{
    extern __shared__ float sm[];
    float* sW = sm;
    float* sX = sm + 16384;
    float* sH = sX + 8192;

    const int tid = threadIdx.x;
    const int n0 = blockIdx.x * NB;

    {
        const float4* nssb = nss4 + (size_t)n0 * 32;
        float4* outS = out + (size_t)n0 * 32;
        for (int i = tid; i < NB * 32; i += 256)
            if (n0 + (i >> 5) < NNODES) outS[i] = nssb[i];
        const float4* nsvb = nsv4 + (size_t)n0 * 96;
        float4* outV = out + (size_t)NNODES * 32 + (size_t)n0 * 96;
        for (int i = tid; i < NB * 96; i += 256)
            if (n0 + i / 96 < NNODES) outV[i] = nsvb[i];
    }

    for (int i = tid; i < NB * 32; i += 256) {
        int n = n0 + (i >> 5);
        ((float4*)sX)[i] = (n < NNODES) ? nss4[(size_t)n * 32 + (i & 31)]
                                        : make_float4(0.f, 0.f, 0.f, 0.f);
    }
    for (int i = tid; i < 4096; i += 256)
        ((float4*)sW)[i] = ((const float4*)W1)[i];
    __syncthreads();

    const int tx = tid & 31, ty = tid >> 5;
    const int c0 = tx * 4;

    u64 acc[8][2];

    #pragma unroll
    for (int i = 0; i < 8; i++) { acc[i][0] = 0ull; acc[i][1] = 0ull; }
    #pragma unroll 8
    for (int k = 0; k < 128; k += 4) {
        const ulonglong2 w0 = *(const ulonglong2*)&sW[(k + 0) * 128 + c0];
        const ulonglong2 w1 = *(const ulonglong2*)&sW[(k + 1) * 128 + c0];
        const ulonglong2 w2 = *(const ulonglong2*)&sW[(k + 2) * 128 + c0];
        const ulonglong2 w3 = *(const ulonglong2*)&sW[(k + 3) * 128 + c0];
        #pragma unroll
        for (int i = 0; i < 8; i++) {
            const float4 xv = *(const float4*)&sX[(ty * 8 + i) * 128 + k];
            const u64 x0 = pack2(xv.x), x1 = pack2(xv.y);
            const u64 x2 = pack2(xv.z), x3 = pack2(xv.w);
            fma2(acc[i][0], x0, w0.x); fma2(acc[i][1], x0, w0.y);
            fma2(acc[i][0], x1, w1.x); fma2(acc[i][1], x1, w1.y);
            fma2(acc[i][0], x2, w2.x); fma2(acc[i][1], x2, w2.y);
            fma2(acc[i][0], x3, w3.x); fma2(acc[i][1], x3, w3.y);
        }
    }
    {
        const float4 bb = __ldg((const float4*)&b1[c0]);
        #pragma unroll
        for (int i = 0; i < 8; i++) {
            const float2 lo = unpack2(acc[i][0]);
            const float2 hi = unpack2(acc[i][1]);
            float4 h = make_float4(lo.x + bb.x, lo.y + bb.y, hi.x + bb.z, hi.y + bb.w);
            h.x = h.x / (1.f + __expf(-h.x));
            h.y = h.y / (1.f + __expf(-h.y));
            h.z = h.z / (1.f + __expf(-h.z));
            h.w = h.w / (1.f + __expf(-h.w));
            *(float4*)&sH[(ty * 8 + i) * 128 + c0] = h;
        }
    }

    for (int t = 0; t < 3; t++) {
        __syncthreads();
        for (int i = tid; i < 4096; i += 256) {
            int k = i >> 5, jj = i & 31;
            ((float4*)sW)[i] = *(const float4*)&W2[(size_t)k * 384 + t * 128 + jj * 4];
        }
        __syncthreads();
        #pragma unroll
        for (int i = 0; i < 8; i++) { acc[i][0] = 0ull; acc[i][1] = 0ull; }
        #pragma unroll 8
        for (int k = 0; k < 128; k += 4) {
            const ulonglong2 w0 = *(const ulonglong2*)&sW[(k + 0) * 128 + c0];
            const ulonglong2 w1 = *(const ulonglong2*)&sW[(k + 1) * 128 + c0];
            const ulonglong2 w2 = *(const ulonglong2*)&sW[(k + 2) * 128 + c0];
            const ulonglong2 w3 = *(const ulonglong2*)&sW[(k + 3) * 128 + c0];
            #pragma unroll
            for (int i = 0; i < 8; i++) {
                const float4 xv = *(const float4*)&sH[(ty * 8 + i) * 128 + k];
                const u64 x0 = pack2(xv.x), x1 = pack2(xv.y);
                const u64 x2 = pack2(xv.z), x3 = pack2(xv.w);
                fma2(acc[i][0], x0, w0.x); fma2(acc[i][1], x0, w0.y);
                fma2(acc[i][0], x1, w1.x); fma2(acc[i][1], x1, w1.y);
                fma2(acc[i][0], x2, w2.x); fma2(acc[i][1], x2, w2.y);
                fma2(acc[i][0], x3, w3.x); fma2(acc[i][1], x3, w3.y);
            }
        }
        const float4 bb = __ldg((const float4*)&b2[t * 128 + c0]);
        #pragma unroll
        for (int i = 0; i < 8; i++) {
            const int n = n0 + ty * 8 + i;
            if (n < NNODES) {
                const float2 lo = unpack2(acc[i][0]);
                const float2 hi = unpack2(acc[i][1]);
                *(float4*)&g_so[(size_t)n * 384 + t * 128 + c0] =
                    make_float4(lo.x + bb.x, lo.y + bb.y, hi.x + bb.z, hi.y + bb.w);
            }
        }
    }
}

// ---------------------------------------------------------------------------
// Slot-centric edge kernel: warp handles 8 consecutive CSR slots per iter.
// Two-phase filter GEMM (SV+EV, then NS) at EPW=8 halves W smem traffic.
// src-sorted slots => src payload gathers hit L1/L2 (high reuse).
// ---------------------------------------------------------------------------
#define EPW 8

__global__ void __launch_bounds__(256, 2) edge_kernel(
    const float* __restrict__ nss, const float* __restrict__ nsv,
    const float* __restrict__ Wf, const float* __restrict__ bf,
    float* __restrict__ out)
{
    __shared__ __align__(16) float sWf[ESZ * 384];
    __shared__ __align__(16) float sbf[384];
    __shared__ __align__(16) float sES[8][EPW * ESZ];

    const int tid = threadIdx.x;
    for (int i = tid; i < ESZ * 384 / 4; i += 256)
        ((float4*)sWf)[i] = ((const float4*)Wf)[i];
    for (int i = tid; i < 96; i += 256)
        ((float4*)sbf)[i] = ((const float4*)bf)[i];
    __syncthreads();

    const int lane = tid & 31;
    const int warp = tid >> 5;
    const int c0   = lane * 4;
    float* sESf = sES[warp];

    const ulonglong2 bS = *(const ulonglong2*)&sbf[c0];
    const ulonglong2 bE = *(const ulonglong2*)&sbf[128 + c0];
    const ulonglong2 bN = *(const ulonglong2*)&sbf[256 + c0];

    float* __restrict__ outS = out;
    float* __restrict__ outV = out + (size_t)NNODES * NSZ;

    // NEDGES % (8 warps * EPW) == 0 -> every warp's 8 slots always valid
    for (int base = blockIdx.x * 64; base < NEDGES; base += gridDim.x * 64) {
        const int s0 = base + warp * EPW;

        // stage 8 edges' edge_state (contiguous, coalesced) into per-warp smem
        __syncwarp();
        {
            const float4* esg = (const float4*)(g_esr + (size_t)s0 * ESZ);
            for (int u = lane; u < EPW * 5; u += 32)
                ((float4*)sESf)[u] = __ldg(&esg[u]);
        }
        __syncwarp();

        // ---------- phase A: gates SV + EV ----------
        u64 aS[EPW][2], aE[EPW][2];
        #pragma unroll
        for (int e = 0; e < EPW; e++) {
            aS[e][0] = bS.x; aS[e][1] = bS.y;
            aE[e][0] = bE.x; aE[e][1] = bE.y;
        }
        #pragma unroll
        for (int k = 0; k < ESZ; k += 4) {
            ulonglong2 wS[4], wE[4];
            #pragma unroll
            for (int q = 0; q < 4; q++) {
                wS[q] = *(const ulonglong2*)&sWf[(k + q) * 384 + c0];
                wE[q] = *(const ulonglong2*)&sWf[(k + q) * 384 + 128 + c0];
            }
            #pragma unroll
            for (int e = 0; e < EPW; e++) {
                const float4 es4 = *(const float4*)&sESf[e * ESZ + k];
                const u64 s0p = pack2(es4.x), s1p = pack2(es4.y);
                const u64 s2p = pack2(es4.z), s3p = pack2(es4.w);
                fma2(aS[e][0], s0p, wS[0].x); fma2(aS[e][1], s0p, wS[0].y);
                fma2(aE[e][0], s0p, wE[0].x); fma2(aE[e][1], s0p, wE[0].y);
                fma2(aS[e][0], s1p, wS[1].x); fma2(aS[e][1], s1p, wS[1].y);
                fma2(aE[e][0], s1p, wE[1].x); fma2(aE[e][1], s1p, wE[1].y);
                fma2(aS[e][0], s2p, wS[2].x); fma2(aS[e][1], s2p, wS[2].y);
                fma2(aE[e][0], s2p, wE[2].x); fma2(aE[e][1], s2p, wE[2].y);
                fma2(aS[e][0], s3p, wS[3].x); fma2(aS[e][1], s3p, wS[3].y);
                fma2(aE[e][0], s3p, wE[3].x); fma2(aE[e][1], s3p, wE[3].y);
            }
        }
        // phase-A epilogue: vector messages
        #pragma unroll
        for (int e = 0; e < EPW; e++) {
            const int slot = s0 + e;
            const float4 mt = __ldg(&g_meta[slot]);
            const int src = __ldg(&g_src[slot]);
            const int dst = __ldg(&g_dst[slot]);
            const float cu = mt.w;

            const float2 p0 = unpack2(aS[e][0]), p1 = unpack2(aS[e][1]);
            const float2 p2 = unpack2(aE[e][0]), p3 = unpack2(aE[e][1]);
            const float4 fSV = make_float4(p0.x*cu, p0.y*cu, p1.x*cu, p1.y*cu);
            const float4 fEV = make_float4(p2.x*cu, p2.y*cu, p3.x*cu, p3.y*cu);

            const float* so = &g_so[(size_t)src * 384];
            const float4 foSV = f4_mul(fSV, __ldg((const float4*)&so[c0]));
            const float4 foEV = f4_mul(fEV, __ldg((const float4*)&so[128 + c0]));

            const float* nv = &nsv[(size_t)src * 384];
            float* ov = &outV[(size_t)dst * 384];
            const float4 xv0 = __ldg((const float4*)&nv[c0]);
            const float4 xv1 = __ldg((const float4*)&nv[128 + c0]);
            const float4 xv2 = __ldg((const float4*)&nv[256 + c0]);
            red4(&ov[c0],       f4_msg(xv0, foSV, mt.x, foEV));
            red4(&ov[128 + c0], f4_msg(xv1, foSV, mt.y, foEV));
            red4(&ov[256 + c0], f4_msg(xv2, foSV, mt.z, foEV));
        }

        // ---------- phase B: gate NS ----------
        u64 aN[EPW][2];
        #pragma unroll
        for (int e = 0; e < EPW; e++) { aN[e][0] = bN.x; aN[e][1] = bN.y; }
        #pragma unroll
        for (int k = 0; k < ESZ; k += 4) {
            ulonglong2 wN[4];
            #pragma unroll
            for (int q = 0; q < 4; q++)
                wN[q] = *(const ulonglong2*)&sWf[(k + q) * 384 + 256 + c0];
            #pragma unroll
            for (int e = 0; e < EPW; e++) {
                const float4 es4 = *(const float4*)&sESf[e * ESZ + k];
                const u64 s0p = pack2(es4.x), s1p = pack2(es4.y);
                const u64 s2p = pack2(es4.z), s3p = pack2(es4.w);
                fma2(aN[e][0], s0p, wN[0].x); fma2(aN[e][1], s0p, wN[0].y);
                fma2(aN[e][0], s1p, wN[1].x); fma2(aN[e][1], s1p, wN[1].y);
                fma2(aN[e][0], s2p, wN[2].x); fma2(aN[e][1], s2p, wN[2].y);
                fma2(aN[e][0], s3p, wN[3].x); fma2(aN[e][1], s3p, wN[3].y);
            }
        }
        // phase-B epilogue: scalar messages
        #pragma unroll
        for (int e = 0; e < EPW; e++) {
            const int slot = s0 + e;
            const float cu = __ldg(&g_meta[slot].w);
            const int src = __ldg(&g_src[slot]);
            const int dst = __ldg(&g_dst[slot]);

            const float2 p4 = unpack2(aN[e][0]), p5 = unpack2(aN[e][1]);
            const float4 fNS = make_float4(p4.x*cu, p4.y*cu, p5.x*cu, p5.y*cu);
            const float4 foNS =
                f4_mul(fNS, __ldg((const float4*)&g_so[(size_t)src * 384 + 256 + c0]));
            const float4 xs = __ldg((const float4*)&nss[(size_t)src * NSZ + c0]);
            red4(&outS[(size_t)dst * NSZ + c0], f4_mul(xs, foNS));
        }
    }
}

// ---------------------------------------------------------------------------
extern "C" void kernel_launch(void* const* d_in, const int* in_sizes, int n_in,
                              void* d_out, int out_size)
{
    const float* nss           = (const float*)d_in[0];
    const float* nsv           = (const float*)d_in[1];
    const float* edge_state    = (const float*)d_in[2];
    const float* edge_vector   = (const float*)d_in[3];
    const float* edge_distance = (const float*)d_in[4];
    const int*   edges         = (const int*)d_in[5];
    const float* W_filter      = (const float*)d_in[6];
    const float* b_filter      = (const float*)d_in[7];
    const float* W1            = (const float*)d_in[8];
    const float* b1            = (const float*)d_in[9];
    const float* W2            = (const float*)d_in[10];
    const float* b2            = (const float*)d_in[11];
    float* out = (float*)d_out;

    csr_zero<<<(NNODES + 256) / 256, 256>>>();
    csr_hist<<<(NEDGES + 255) / 256, 256>>>(edges);
    csr_scan<<<1, 1024>>>();
    csr_scatter<<<(NEDGES + 255) / 256, 256>>>(edges, edge_vector, edge_distance,
                                               (const float4*)edge_state);

    const int smem1 = (16384 + 2 * NB * 128) * sizeof(float);
    cudaFuncSetAttribute(node_mlp, cudaFuncAttributeMaxDynamicSharedMemorySize, smem1);
    node_mlp<<<(NNODES + NB - 1) / NB, 256, smem1>>>(
        (const float4*)nss, (const float4*)nsv, W1, b1, W2, b2, (float4*)out);

    edge_kernel<<<592, 256>>>(nss, nsv, W_filter, b_filter, out);
}

// round 8
// speedup vs baseline: 1.6471x; 1.6471x over previous
#include <cuda_runtime.h>
#include <math.h>
#include <cstdint>

#define NNODES 20000
#define NEDGES 640000
#define NSZ 128
#define ESZ 20
#define CUTF 5.0f

// ---------------- device scratch ----------------
__device__ float g_so[NNODES * 384];
__device__ int g_hist[NNODES + 1];
__device__ int g_row[NNODES + 1];
__device__ int g_off[NNODES];
__device__ int g_dst[NEDGES];
__device__ int g_src[NEDGES];
__device__ float4 g_meta[NEDGES];        // (en0, en1, en2, cutoff)
__device__ float g_esr[NEDGES * ESZ];    // edge_state in CSR slot order

typedef unsigned long long u64;

// ---------------- helpers ----------------
__device__ __forceinline__ void fma2(u64& d, u64 a, u64 b) {
    asm("fma.rn.f32x2 %0, %1, %2, %0;" : "+l"(d) : "l"(a), "l"(b));
}
__device__ __forceinline__ u64 pack2(float x) {
    u64 r; asm("mov.b64 %0, {%1, %1};" : "=l"(r) : "f"(x)); return r;
}
__device__ __forceinline__ float2 unpack2(u64 a) {
    float2 f; asm("mov.b64 {%0, %1}, %2;" : "=f"(f.x), "=f"(f.y) : "l"(a));
    return f;
}
__device__ __forceinline__ float4 f4_mul(float4 a, float4 b) {
    return make_float4(a.x*b.x, a.y*b.y, a.z*b.z, a.w*b.w);
}
__device__ __forceinline__ float4 f4_msg(float4 xv, float4 g, float s, float4 f) {
    return make_float4(fmaf(xv.x, g.x, s*f.x), fmaf(xv.y, g.y, s*f.y),
                       fmaf(xv.z, g.z, s*f.z), fmaf(xv.w, g.w, s*f.w));
}
__device__ __forceinline__ void red4(float* p, float4 v) {
    asm volatile("red.global.add.v4.f32 [%0], {%1, %2, %3, %4};"
                 :: "l"(p), "f"(v.x), "f"(v.y), "f"(v.z), "f"(v.w) : "memory");
}

// ---------------------------------------------------------------------------
// CSR build (keyed by src) + edge pre-gather into CSR order
// ---------------------------------------------------------------------------
__global__ void csr_zero() {
    int i = blockIdx.x * 256 + threadIdx.x;
    if (i <= NNODES) g_hist[i] = 0;
}
__global__ void csr_hist(const int* __restrict__ edges) {
    int i = blockIdx.x * 256 + threadIdx.x;
    if (i < NEDGES) atomicAdd(&g_hist[edges[2 * i]], 1);
}
__global__ void __launch_bounds__(1024) csr_scan() {
    __shared__ int s[1024];
    const int t = threadIdx.x;
    const int C = 20;
    const int base = t * C;
    int sum = 0;
    #pragma unroll
    for (int j = 0; j < C; j++) {
        int idx = base + j;
        if (idx < NNODES) sum += g_hist[idx];
    }
    s[t] = sum;
    __syncthreads();
    for (int off = 1; off < 1024; off <<= 1) {
        int v = (t >= off) ? s[t - off] : 0;
        __syncthreads();
        s[t] += v;
        __syncthreads();
    }
    int run = s[t] - sum;
    #pragma unroll
    for (int j = 0; j < C; j++) {
        int idx = base + j;
        if (idx < NNODES) {
            g_row[idx] = run;
            g_off[idx] = run;
            run += g_hist[idx];
        }
    }
    if (t == 1023) g_row[NNODES] = NEDGES;
}
__global__ void csr_scatter(const int* __restrict__ edges,
                            const float* __restrict__ edge_vector,
                            const float* __restrict__ edge_distance,
                            const float4* __restrict__ edge_state4)
{
    int i = blockIdx.x * 256 + threadIdx.x;
    if (i >= NEDGES) return;
    const int s = edges[2 * i];
    const int d = edges[2 * i + 1];
    const int p = atomicAdd(&g_off[s], 1);
    g_dst[p] = d;
    g_src[p] = s;

    const float v0 = __ldg(&edge_vector[3 * i]);
    const float v1 = __ldg(&edge_vector[3 * i + 1]);
    const float v2 = __ldg(&edge_vector[3 * i + 2]);
    const float inv = 1.0f / fmaxf(sqrtf(v0*v0 + v1*v1 + v2*v2), 1e-12f);
    const float dist = __ldg(&edge_distance[i]);
    const float cu = (dist < CUTF)
        ? 0.5f * (__cosf(3.14159265358979f * dist * (1.0f / CUTF)) + 1.0f) : 0.0f;
    g_meta[p] = make_float4(v0 * inv, v1 * inv, v2 * inv, cu);

    float4* dst4 = (float4*)&g_esr[(size_t)p * ESZ];
    #pragma unroll
    for (int c = 0; c < 5; c++) dst4[c] = __ldg(&edge_state4[(size_t)i * 5 + c]);
}

// ---------------------------------------------------------------------------
// node MLP (f32x2) + init-out fold
// ---------------------------------------------------------------------------
#define NB 64

__global__ void __launch_bounds__(256) node_mlp(
    const float4* __restrict__ nss4, const float4* __restrict__ nsv4,
    const float* __restrict__ W1, const float* __restrict__ b1,
    const float* __restrict__ W2, const float* __restrict__ b2,
    float4* __restrict__ out)
{
    extern __shared__ float sm[];
    float* sW = sm;
    float* sX = sm + 16384;
    float* sH = sX + 8192;

    const int tid = threadIdx.x;
    const int n0 = blockIdx.x * NB;

    {
        const float4* nssb = nss4 + (size_t)n0 * 32;
        float4* outS = out + (size_t)n0 * 32;
        for (int i = tid; i < NB * 32; i += 256)
            if (n0 + (i >> 5) < NNODES) outS[i] = nssb[i];
        const float4* nsvb = nsv4 + (size_t)n0 * 96;
        float4* outV = out + (size_t)NNODES * 32 + (size_t)n0 * 96;
        for (int i = tid; i < NB * 96; i += 256)
            if (n0 + i / 96 < NNODES) outV[i] = nsvb[i];
    }

    for (int i = tid; i < NB * 32; i += 256) {
        int n = n0 + (i >> 5);
        ((float4*)sX)[i] = (n < NNODES) ? nss4[(size_t)n * 32 + (i & 31)]
                                        : make_float4(0.f, 0.f, 0.f, 0.f);
    }
    for (int i = tid; i < 4096; i += 256)
        ((float4*)sW)[i] = ((const float4*)W1)[i];
    __syncthreads();

    const int tx = tid & 31, ty = tid >> 5;
    const int c0 = tx * 4;

    u64 acc[8][2];

    #pragma unroll
    for (int i = 0; i < 8; i++) { acc[i][0] = 0ull; acc[i][1] = 0ull; }
    #pragma unroll 8
    for (int k = 0; k < 128; k += 4) {
        const ulonglong2 w0 = *(const ulonglong2*)&sW[(k + 0) * 128 + c0];
        const ulonglong2 w1 = *(const ulonglong2*)&sW[(k + 1) * 128 + c0];
        const ulonglong2 w2 = *(const ulonglong2*)&sW[(k + 2) * 128 + c0];
        const ulonglong2 w3 = *(const ulonglong2*)&sW[(k + 3) * 128 + c0];
        #pragma unroll
        for (int i = 0; i < 8; i++) {
            const float4 xv = *(const float4*)&sX[(ty * 8 + i) * 128 + k];
            const u64 x0 = pack2(xv.x), x1 = pack2(xv.y);
            const u64 x2 = pack2(xv.z), x3 = pack2(xv.w);
            fma2(acc[i][0], x0, w0.x); fma2(acc[i][1], x0, w0.y);
            fma2(acc[i][0], x1, w1.x); fma2(acc[i][1], x1, w1.y);
            fma2(acc[i][0], x2, w2.x); fma2(acc[i][1], x2, w2.y);
            fma2(acc[i][0], x3, w3.x); fma2(acc[i][1], x3, w3.y);
        }
    }
    {
        const float4 bb = __ldg((const float4*)&b1[c0]);
        #pragma unroll
        for (int i = 0; i < 8; i++) {
            const float2 lo = unpack2(acc[i][0]);
            const float2 hi = unpack2(acc[i][1]);
            float4 h = make_float4(lo.x + bb.x, lo.y + bb.y, hi.x + bb.z, hi.y + bb.w);
            h.x = h.x / (1.f + __expf(-h.x));
            h.y = h.y / (1.f + __expf(-h.y));
            h.z = h.z / (1.f + __expf(-h.z));
            h.w = h.w / (1.f + __expf(-h.w));
            *(float4*)&sH[(ty * 8 + i) * 128 + c0] = h;
        }
    }

    for (int t = 0; t < 3; t++) {
        __syncthreads();
        for (int i = tid; i < 4096; i += 256) {
            int k = i >> 5, jj = i & 31;
            ((float4*)sW)[i] = *(const float4*)&W2[(size_t)k * 384 + t * 128 + jj * 4];
        }
        __syncthreads();
        #pragma unroll
        for (int i = 0; i < 8; i++) { acc[i][0] = 0ull; acc[i][1] = 0ull; }
        #pragma unroll 8
        for (int k = 0; k < 128; k += 4) {
            const ulonglong2 w0 = *(const ulonglong2*)&sW[(k + 0) * 128 + c0];
            const ulonglong2 w1 = *(const ulonglong2*)&sW[(k + 1) * 128 + c0];
            const ulonglong2 w2 = *(const ulonglong2*)&sW[(k + 2) * 128 + c0];
            const ulonglong2 w3 = *(const ulonglong2*)&sW[(k + 3) * 128 + c0];
            #pragma unroll
            for (int i = 0; i < 8; i++) {
                const float4 xv = *(const float4*)&sH[(ty * 8 + i) * 128 + k];
                const u64 x0 = pack2(xv.x), x1 = pack2(xv.y);
                const u64 x2 = pack2(xv.z), x3 = pack2(xv.w);
                fma2(acc[i][0], x0, w0.x); fma2(acc[i][1], x0, w0.y);
                fma2(acc[i][0], x1, w1.x); fma2(acc[i][1], x1, w1.y);
                fma2(acc[i][0], x2, w2.x); fma2(acc[i][1], x2, w2.y);
                fma2(acc[i][0], x3, w3.x); fma2(acc[i][1], x3, w3.y);
            }
        }
        const float4 bb = __ldg((const float4*)&b2[t * 128 + c0]);
        #pragma unroll
        for (int i = 0; i < 8; i++) {
            const int n = n0 + ty * 8 + i;
            if (n < NNODES) {
                const float2 lo = unpack2(acc[i][0]);
                const float2 hi = unpack2(acc[i][1]);
                *(float4*)&g_so[(size_t)n * 384 + t * 128 + c0] =
                    make_float4(lo.x + bb.x, lo.y + bb.y, hi.x + bb.z, hi.y + bb.w);
            }
        }
    }
}

// ---------------------------------------------------------------------------
// Edge kernel (round-2 structure: EPW=4, 4 warps/block, single-phase f32x2)
// reading CSR-src-sorted pre-gathered arrays for gather locality.
// ---------------------------------------------------------------------------
#define EPW 4

__global__ void __launch_bounds__(128) edge_kernel(
    const float* __restrict__ nss, const float* __restrict__ nsv,
    const float* __restrict__ Wf, const float* __restrict__ bf,
    float* __restrict__ out)
{
    __shared__ __align__(16) float sWf[ESZ * 384];
    __shared__ __align__(16) float sbf[384];
    __shared__ __align__(16) float sES[4][EPW * ESZ];

    const int tid = threadIdx.x;
    for (int i = tid; i < ESZ * 384 / 4; i += 128)
        ((float4*)sWf)[i] = ((const float4*)Wf)[i];
    for (int i = tid; i < 96; i += 128)
        ((float4*)sbf)[i] = ((const float4*)bf)[i];
    __syncthreads();

    const int lane  = tid & 31;
    const int warp  = tid >> 5;
    const int gwarp = blockIdx.x * 4 + warp;
    const int nwarp = gridDim.x * 4;
    const int c0    = lane * 4;
    float* myES = sES[warp];

    const ulonglong2 bS = *(const ulonglong2*)&sbf[c0];
    const ulonglong2 bE = *(const ulonglong2*)&sbf[128 + c0];
    const ulonglong2 bN = *(const ulonglong2*)&sbf[256 + c0];

    float* __restrict__ outS = out;
    float* __restrict__ outV = out + (size_t)NNODES * NSZ;

    // NEDGES % EPW == 0 and stride divides evenly -> all slots valid
    for (int s0 = gwarp * EPW; s0 < NEDGES; s0 += nwarp * EPW) {
        // stage EPW edges' edge_state (contiguous, coalesced)
        __syncwarp();
        if (lane < EPW * 5) {
            ((float4*)myES)[lane] =
                __ldg((const float4*)(g_esr + (size_t)s0 * ESZ) + lane);
        }
        __syncwarp();

        // filter GEMM: acc = bf + es @ Wf (packed f32x2)
        u64 acc[EPW][6];
        #pragma unroll
        for (int e = 0; e < EPW; e++) {
            acc[e][0] = bS.x; acc[e][1] = bS.y;
            acc[e][2] = bE.x; acc[e][3] = bE.y;
            acc[e][4] = bN.x; acc[e][5] = bN.y;
        }
        #pragma unroll
        for (int k = 0; k < ESZ; k++) {
            const ulonglong2 wS = *(const ulonglong2*)&sWf[k * 384 + c0];
            const ulonglong2 wE = *(const ulonglong2*)&sWf[k * 384 + 128 + c0];
            const ulonglong2 wN = *(const ulonglong2*)&sWf[k * 384 + 256 + c0];
            #pragma unroll
            for (int e = 0; e < EPW; e++) {
                const u64 s2 = pack2(myES[e * ESZ + k]);
                fma2(acc[e][0], s2, wS.x); fma2(acc[e][1], s2, wS.y);
                fma2(acc[e][2], s2, wE.x); fma2(acc[e][3], s2, wE.y);
                fma2(acc[e][4], s2, wN.x); fma2(acc[e][5], s2, wN.y);
            }
        }

        // per-edge gather + message + scatter (srcs repeat across slots -> L1 hits)
        #pragma unroll
        for (int e = 0; e < EPW; e++) {
            const int slot = s0 + e;
            const float4 mt = __ldg(&g_meta[slot]);
            const int src = __ldg(&g_src[slot]);
            const int dst = __ldg(&g_dst[slot]);
            const float cu = mt.w;

            float2 p0 = unpack2(acc[e][0]), p1 = unpack2(acc[e][1]);
            float2 p2 = unpack2(acc[e][2]), p3 = unpack2(acc[e][3]);
            float2 p4 = unpack2(acc[e][4]), p5 = unpack2(acc[e][5]);
            float4 fSV = make_float4(p0.x*cu, p0.y*cu, p1.x*cu, p1.y*cu);
            float4 fEV = make_float4(p2.x*cu, p2.y*cu, p3.x*cu, p3.y*cu);
            float4 fNS = make_float4(p4.x*cu, p4.y*cu, p5.x*cu, p5.y*cu);

            const float* so = &g_so[(size_t)src * 384];
            const float4 foSV = f4_mul(fSV, *(const float4*)&so[c0]);
            const float4 foEV = f4_mul(fEV, *(const float4*)&so[128 + c0]);
            const float4 foNS = f4_mul(fNS, *(const float4*)&so[256 + c0]);

            // scalar message
            const float4 xs = *(const float4*)&nss[(size_t)src * NSZ + c0];
            red4(&outS[(size_t)dst * NSZ + c0], f4_mul(xs, foNS));

            // vector messages
            const float* nv = &nsv[(size_t)src * 384];
            float* ov = &outV[(size_t)dst * 384];
            {
                const float4 xv = *(const float4*)&nv[c0];
                red4(&ov[c0], f4_msg(xv, foSV, mt.x, foEV));
            }
            {
                const float4 xv = *(const float4*)&nv[128 + c0];
                red4(&ov[128 + c0], f4_msg(xv, foSV, mt.y, foEV));
            }
            {
                const float4 xv = *(const float4*)&nv[256 + c0];
                red4(&ov[256 + c0], f4_msg(xv, foSV, mt.z, foEV));
            }
        }
    }
}

// ---------------------------------------------------------------------------
extern "C" void kernel_launch(void* const* d_in, const int* in_sizes, int n_in,
                              void* d_out, int out_size)
{
    const float* nss           = (const float*)d_in[0];
    const float* nsv           = (const float*)d_in[1];
    const float* edge_state    = (const float*)d_in[2];
    const float* edge_vector   = (const float*)d_in[3];
    const float* edge_distance = (const float*)d_in[4];
    const int*   edges         = (const int*)d_in[5];
    const float* W_filter      = (const float*)d_in[6];
    const float* b_filter      = (const float*)d_in[7];
    const float* W1            = (const float*)d_in[8];
    const float* b1            = (const float*)d_in[9];
    const float* W2            = (const float*)d_in[10];
    const float* b2            = (const float*)d_in[11];
    float* out = (float*)d_out;

    csr_zero<<<(NNODES + 256) / 256, 256>>>();
    csr_hist<<<(NEDGES + 255) / 256, 256>>>(edges);
    csr_scan<<<1, 1024>>>();
    csr_scatter<<<(NEDGES + 255) / 256, 256>>>(edges, edge_vector, edge_distance,
                                               (const float4*)edge_state);

    const int smem1 = (16384 + 2 * NB * 128) * sizeof(float);
    cudaFuncSetAttribute(node_mlp, cudaFuncAttributeMaxDynamicSharedMemorySize, smem1);
    node_mlp<<<(NNODES + NB - 1) / NB, 256, smem1>>>(
        (const float4*)nss, (const float4*)nsv, W1, b1, W2, b2, (float4*)out);

    edge_kernel<<<1480, 128>>>(nss, nsv, W_filter, b_filter, out);
}

// round 9
// speedup vs baseline: 1.8790x; 1.1408x over previous
#include <cuda_runtime.h>
#include <math.h>
#include <cstdint>

#define NNODES 20000
#define NEDGES 640000
#define NSZ 128
#define ESZ 20
#define CUTF 5.0f

// ---------------- device scratch (precomputed node-side gate payloads) ----
__device__ float g_dsv[NNODES * 384];   // nsv  ⊙ soSV   [node][3][128]
__device__ float g_sev[NNODES * 128];   // soEV          [node][128]
__device__ float g_cns[NNODES * 128];   // nss  ⊙ soNS   [node][128]

typedef unsigned long long u64;

// ---------------- helpers ----------------
__device__ __forceinline__ void fma2(u64& d, u64 a, u64 b) {
    asm("fma.rn.f32x2 %0, %1, %2, %0;" : "+l"(d) : "l"(a), "l"(b));
}
__device__ __forceinline__ u64 pack2(float x) {
    u64 r; asm("mov.b64 %0, {%1, %1};" : "=l"(r) : "f"(x)); return r;
}
__device__ __forceinline__ float2 unpack2(u64 a) {
    float2 f; asm("mov.b64 {%0, %1}, %2;" : "=f"(f.x), "=f"(f.y) : "l"(a));
    return f;
}
__device__ __forceinline__ float4 f4_mul(float4 a, float4 b) {
    return make_float4(a.x*b.x, a.y*b.y, a.z*b.z, a.w*b.w);
}
// xv * g + s * f
__device__ __forceinline__ float4 f4_msg(float4 xv, float4 g, float s, float4 f) {
    return make_float4(fmaf(xv.x, g.x, s*f.x), fmaf(xv.y, g.y, s*f.y),
                       fmaf(xv.z, g.z, s*f.z), fmaf(xv.w, g.w, s*f.w));
}
__device__ __forceinline__ void red4(float* p, float4 v) {
    asm volatile("red.global.add.v4.f32 [%0], {%1, %2, %3, %4};"
                 :: "l"(p), "f"(v.x), "f"(v.y), "f"(v.z), "f"(v.w) : "memory");
}

// ---------------------------------------------------------------------------
// Kernel 1: scalar_output tiles fused with node-side gate payloads:
//   t=0: soSV -> D_SV = nsv ⊙ soSV   (3 x 128 per node)
//   t=1: soEV -> stored raw
//   t=2: soNS -> C_NS = nss ⊙ soNS
// Also copies [nss | nsv] into out (init fold).
// ---------------------------------------------------------------------------
#define NB 64

__global__ void __launch_bounds__(256) node_mlp(
    const float4* __restrict__ nss4, const float4* __restrict__ nsv4,
    const float* __restrict__ W1, const float* __restrict__ b1,
    const float* __restrict__ W2, const float* __restrict__ b2,
    float4* __restrict__ out)
{
    extern __shared__ float sm[];
    float* sW = sm;              // 16384
    float* sX = sm + 16384;      // 8192  (node scalars, reused for C_NS)
    float* sH = sX + 8192;       // 8192

    const int tid = threadIdx.x;
    const int n0 = blockIdx.x * NB;

    // init-out fold
    {
        const float4* nssb = nss4 + (size_t)n0 * 32;
        float4* outS = out + (size_t)n0 * 32;
        for (int i = tid; i < NB * 32; i += 256)
            if (n0 + (i >> 5) < NNODES) outS[i] = nssb[i];
        const float4* nsvb = nsv4 + (size_t)n0 * 96;
        float4* outV = out + (size_t)NNODES * 32 + (size_t)n0 * 96;
        for (int i = tid; i < NB * 96; i += 256)
            if (n0 + i / 96 < NNODES) outV[i] = nsvb[i];
    }

    for (int i = tid; i < NB * 32; i += 256) {
        int n = n0 + (i >> 5);
        ((float4*)sX)[i] = (n < NNODES) ? nss4[(size_t)n * 32 + (i & 31)]
                                        : make_float4(0.f, 0.f, 0.f, 0.f);
    }
    for (int i = tid; i < 4096; i += 256)
        ((float4*)sW)[i] = ((const float4*)W1)[i];
    __syncthreads();

    const int tx = tid & 31, ty = tid >> 5;
    const int c0 = tx * 4;

    u64 acc[8][2];

    // phase 1: H = silu(X @ W1 + b1)
    #pragma unroll
    for (int i = 0; i < 8; i++) { acc[i][0] = 0ull; acc[i][1] = 0ull; }
    #pragma unroll 8
    for (int k = 0; k < 128; k += 4) {
        const ulonglong2 w0 = *(const ulonglong2*)&sW[(k + 0) * 128 + c0];
        const ulonglong2 w1 = *(const ulonglong2*)&sW[(k + 1) * 128 + c0];
        const ulonglong2 w2 = *(const ulonglong2*)&sW[(k + 2) * 128 + c0];
        const ulonglong2 w3 = *(const ulonglong2*)&sW[(k + 3) * 128 + c0];
        #pragma unroll
        for (int i = 0; i < 8; i++) {
            const float4 xv = *(const float4*)&sX[(ty * 8 + i) * 128 + k];
            const u64 x0 = pack2(xv.x), x1 = pack2(xv.y);
            const u64 x2 = pack2(xv.z), x3 = pack2(xv.w);
            fma2(acc[i][0], x0, w0.x); fma2(acc[i][1], x0, w0.y);
            fma2(acc[i][0], x1, w1.x); fma2(acc[i][1], x1, w1.y);
            fma2(acc[i][0], x2, w2.x); fma2(acc[i][1], x2, w2.y);
            fma2(acc[i][0], x3, w3.x); fma2(acc[i][1], x3, w3.y);
        }
    }
    {
        const float4 bb = __ldg((const float4*)&b1[c0]);
        #pragma unroll
        for (int i = 0; i < 8; i++) {
            const float2 lo = unpack2(acc[i][0]);
            const float2 hi = unpack2(acc[i][1]);
            float4 h = make_float4(lo.x + bb.x, lo.y + bb.y, hi.x + bb.z, hi.y + bb.w);
            h.x = h.x / (1.f + __expf(-h.x));
            h.y = h.y / (1.f + __expf(-h.y));
            h.z = h.z / (1.f + __expf(-h.z));
            h.w = h.w / (1.f + __expf(-h.w));
            *(float4*)&sH[(ty * 8 + i) * 128 + c0] = h;
        }
    }

    // phase 2: three output tiles with fused gate payloads
    for (int t = 0; t < 3; t++) {
        __syncthreads();
        for (int i = tid; i < 4096; i += 256) {
            int k = i >> 5, jj = i & 31;
            ((float4*)sW)[i] = *(const float4*)&W2[(size_t)k * 384 + t * 128 + jj * 4];
        }
        __syncthreads();
        #pragma unroll
        for (int i = 0; i < 8; i++) { acc[i][0] = 0ull; acc[i][1] = 0ull; }
        #pragma unroll 8
        for (int k = 0; k < 128; k += 4) {
            const ulonglong2 w0 = *(const ulonglong2*)&sW[(k + 0) * 128 + c0];
            const ulonglong2 w1 = *(const ulonglong2*)&sW[(k + 1) * 128 + c0];
            const ulonglong2 w2 = *(const ulonglong2*)&sW[(k + 2) * 128 + c0];
            const ulonglong2 w3 = *(const ulonglong2*)&sW[(k + 3) * 128 + c0];
            #pragma unroll
            for (int i = 0; i < 8; i++) {
                const float4 xv = *(const float4*)&sH[(ty * 8 + i) * 128 + k];
                const u64 x0 = pack2(xv.x), x1 = pack2(xv.y);
                const u64 x2 = pack2(xv.z), x3 = pack2(xv.w);
                fma2(acc[i][0], x0, w0.x); fma2(acc[i][1], x0, w0.y);
                fma2(acc[i][0], x1, w1.x); fma2(acc[i][1], x1, w1.y);
                fma2(acc[i][0], x2, w2.x); fma2(acc[i][1], x2, w2.y);
                fma2(acc[i][0], x3, w3.x); fma2(acc[i][1], x3, w3.y);
            }
        }
        const float4 bb = __ldg((const float4*)&b2[t * 128 + c0]);
        #pragma unroll
        for (int i = 0; i < 8; i++) {
            const int ln = ty * 8 + i;
            const int n = n0 + ln;
            if (n >= NNODES) continue;
            const float2 lo = unpack2(acc[i][0]);
            const float2 hi = unpack2(acc[i][1]);
            const float4 so = make_float4(lo.x + bb.x, lo.y + bb.y,
                                          hi.x + bb.z, hi.y + bb.w);
            if (t == 0) {
                // D_SV = nsv ⊙ soSV (3 spatial dims)
                #pragma unroll
                for (int d3 = 0; d3 < 3; d3++) {
                    const float4 xv =
                        __ldg((const float4*)((const float*)nsv4 +
                                              (size_t)n * 384 + d3 * 128 + c0));
                    *(float4*)&g_dsv[(size_t)n * 384 + d3 * 128 + c0] =
                        f4_mul(xv, so);
                }
            } else if (t == 1) {
                *(float4*)&g_sev[(size_t)n * 128 + c0] = so;
            } else {
                const float4 xs = *(const float4*)&sX[ln * 128 + c0];
                *(float4*)&g_cns[(size_t)n * 128 + c0] = f4_mul(xs, so);
            }
        }
    }
}

// ---------------------------------------------------------------------------
// Kernel 2: per-edge filter (f32x2, EPW=4) + fused-gate messages + RED scatter
// (round-2 structure; payload reads reduced to 5 float4 rows per edge)
// ---------------------------------------------------------------------------
#define EPW 4

__global__ void __launch_bounds__(128) edge_kernel(
    const float* __restrict__ edge_state, const float* __restrict__ edge_vector,
    const float* __restrict__ edge_distance, const int* __restrict__ edges,
    const float* __restrict__ Wf, const float* __restrict__ bf,
    float* __restrict__ out)
{
    __shared__ __align__(16) float sWf[ESZ * 384];
    __shared__ __align__(16) float sbf[384];
    __shared__ __align__(16) float sES[4][EPW * ESZ];

    const int tid = threadIdx.x;
    for (int i = tid; i < ESZ * 384 / 4; i += 128)
        ((float4*)sWf)[i] = ((const float4*)Wf)[i];
    for (int i = tid; i < 96; i += 128)
        ((float4*)sbf)[i] = ((const float4*)bf)[i];
    __syncthreads();

    const int lane  = tid & 31;
    const int warp  = tid >> 5;
    const int gwarp = blockIdx.x * 4 + warp;
    const int nwarp = gridDim.x * 4;
    const int c0    = lane * 4;
    float* myES = sES[warp];

    const ulonglong2 bS = *(const ulonglong2*)&sbf[c0];
    const ulonglong2 bE = *(const ulonglong2*)&sbf[128 + c0];
    const ulonglong2 bN = *(const ulonglong2*)&sbf[256 + c0];

    float* __restrict__ outS = out;
    float* __restrict__ outV = out + (size_t)NNODES * NSZ;

    for (int e0 = gwarp * EPW; e0 < NEDGES; e0 += nwarp * EPW) {
        // stage EPW edges' edge_state (contiguous, coalesced)
        __syncwarp();
        if (lane < EPW * 5) {
            ((float4*)myES)[lane] =
                __ldg((const float4*)&edge_state[(size_t)e0 * ESZ] + lane);
        }
        __syncwarp();

        // filter GEMM: acc = bf + es @ Wf (packed f32x2)
        u64 acc[EPW][6];
        #pragma unroll
        for (int e = 0; e < EPW; e++) {
            acc[e][0] = bS.x; acc[e][1] = bS.y;
            acc[e][2] = bE.x; acc[e][3] = bE.y;
            acc[e][4] = bN.x; acc[e][5] = bN.y;
        }
        #pragma unroll
        for (int k = 0; k < ESZ; k++) {
            const ulonglong2 wS = *(const ulonglong2*)&sWf[k * 384 + c0];
            const ulonglong2 wE = *(const ulonglong2*)&sWf[k * 384 + 128 + c0];
            const ulonglong2 wN = *(const ulonglong2*)&sWf[k * 384 + 256 + c0];
            #pragma unroll
            for (int e = 0; e < EPW; e++) {
                const u64 s2 = pack2(myES[e * ESZ + k]);
                fma2(acc[e][0], s2, wS.x); fma2(acc[e][1], s2, wS.y);
                fma2(acc[e][2], s2, wE.x); fma2(acc[e][3], s2, wE.y);
                fma2(acc[e][4], s2, wN.x); fma2(acc[e][5], s2, wN.y);
            }
        }

        // per-edge fused-gate messages + scatter
        #pragma unroll
        for (int e = 0; e < EPW; e++) {
            const int ed  = e0 + e;
            const int src = __ldg(&edges[2 * ed]);
            const int dst = __ldg(&edges[2 * ed + 1]);

            const float d = __ldg(&edge_distance[ed]);
            const float cu = (d < CUTF)
                ? 0.5f * (__cosf(3.14159265358979f * d * (1.0f / CUTF)) + 1.0f)
                : 0.0f;

            const float v0 = __ldg(&edge_vector[3 * ed]);
            const float v1 = __ldg(&edge_vector[3 * ed + 1]);
            const float v2 = __ldg(&edge_vector[3 * ed + 2]);
            const float nrm = sqrtf(v0 * v0 + v1 * v1 + v2 * v2);
            const float inv = 1.0f / fmaxf(nrm, 1e-12f);
            const float en0 = v0 * inv, en1 = v1 * inv, en2 = v2 * inv;

            float2 p0 = unpack2(acc[e][0]), p1 = unpack2(acc[e][1]);
            float2 p2 = unpack2(acc[e][2]), p3 = unpack2(acc[e][3]);
            float2 p4 = unpack2(acc[e][4]), p5 = unpack2(acc[e][5]);
            const float4 fSV = make_float4(p0.x*cu, p0.y*cu, p1.x*cu, p1.y*cu);
            const float4 fEV = make_float4(p2.x*cu, p2.y*cu, p3.x*cu, p3.y*cu);
            const float4 fNS = make_float4(p4.x*cu, p4.y*cu, p5.x*cu, p5.y*cu);

            // payload: 5 float4 rows (sev, cns, dsv x3)
            const float4 sev = __ldg((const float4*)&g_sev[(size_t)src * 128 + c0]);
            const float4 cns = __ldg((const float4*)&g_cns[(size_t)src * 128 + c0]);
            const float* dsv = &g_dsv[(size_t)src * 384];
            const float4 dv0 = __ldg((const float4*)&dsv[c0]);
            const float4 dv1 = __ldg((const float4*)&dsv[128 + c0]);
            const float4 dv2 = __ldg((const float4*)&dsv[256 + c0]);

            const float4 tE = f4_mul(fEV, sev);   // fwEV ⊙ soEV (hoisted)

            // scalar message
            red4(&outS[(size_t)dst * NSZ + c0], f4_mul(fNS, cns));

            // vector messages
            float* ov = &outV[(size_t)dst * 384];
            red4(&ov[c0],       f4_msg(dv0, fSV, en0, tE));
            red4(&ov[128 + c0], f4_msg(dv1, fSV, en1, tE));
            red4(&ov[256 + c0], f4_msg(dv2, fSV, en2, tE));
        }
    }
}

// ---------------------------------------------------------------------------
extern "C" void kernel_launch(void* const* d_in, const int* in_sizes, int n_in,
                              void* d_out, int out_size)
{
    const float* nss           = (const float*)d_in[0];
    const float* nsv           = (const float*)d_in[1];
    const float* edge_state    = (const float*)d_in[2];
    const float* edge_vector   = (const float*)d_in[3];
    const float* edge_distance = (const float*)d_in[4];
    const int*   edges         = (const int*)d_in[5];
    const float* W_filter      = (const float*)d_in[6];
    const float* b_filter      = (const float*)d_in[7];
    const float* W1            = (const float*)d_in[8];
    const float* b1            = (const float*)d_in[9];
    const float* W2            = (const float*)d_in[10];
    const float* b2            = (const float*)d_in[11];
    float* out = (float*)d_out;

    const int smem1 = (16384 + 2 * NB * 128) * sizeof(float);  // 128 KB
    cudaFuncSetAttribute(node_mlp, cudaFuncAttributeMaxDynamicSharedMemorySize, smem1);
    node_mlp<<<(NNODES + NB - 1) / NB, 256, smem1>>>(
        (const float4*)nss, (const float4*)nsv, W1, b1, W2, b2, (float4*)out);

    edge_kernel<<<1480, 128>>>(edge_state, edge_vector, edge_distance,
                               edges, W_filter, b_filter, out);
}

// round 10
// speedup vs baseline: 2.1240x; 1.1304x over previous
#include <cuda_runtime.h>
#include <math.h>
#include <cstdint>

#define NNODES 20000
#define NEDGES 640000
#define NSZ 128
#define ESZ 20
#define CUTF 5.0f

// ---------------- device scratch (precomputed node-side gate payloads) ----
__device__ float g_dsv[NNODES * 384];   // nsv  ⊙ soSV   [node][3][128]
__device__ float g_sev[NNODES * 128];   // soEV          [node][128]
__device__ float g_cns[NNODES * 128];   // nss  ⊙ soNS   [node][128]

typedef unsigned long long u64;

// ---------------- helpers ----------------
__device__ __forceinline__ void fma2(u64& d, u64 a, u64 b) {
    asm("fma.rn.f32x2 %0, %1, %2, %0;" : "+l"(d) : "l"(a), "l"(b));
}
__device__ __forceinline__ u64 pack2(float x) {
    u64 r; asm("mov.b64 %0, {%1, %1};" : "=l"(r) : "f"(x)); return r;
}
__device__ __forceinline__ float2 unpack2(u64 a) {
    float2 f; asm("mov.b64 {%0, %1}, %2;" : "=f"(f.x), "=f"(f.y) : "l"(a));
    return f;
}
__device__ __forceinline__ float4 f4_mul(float4 a, float4 b) {
    return make_float4(a.x*b.x, a.y*b.y, a.z*b.z, a.w*b.w);
}
// xv * g + s * f
__device__ __forceinline__ float4 f4_msg(float4 xv, float4 g, float s, float4 f) {
    return make_float4(fmaf(xv.x, g.x, s*f.x), fmaf(xv.y, g.y, s*f.y),
                       fmaf(xv.z, g.z, s*f.z), fmaf(xv.w, g.w, s*f.w));
}
__device__ __forceinline__ void red4(float* p, float4 v) {
    asm volatile("red.global.add.v4.f32 [%0], {%1, %2, %3, %4};"
                 :: "l"(p), "f"(v.x), "f"(v.y), "f"(v.z), "f"(v.w) : "memory");
}

// ---------------------------------------------------------------------------
// Kernel 1: scalar_output tiles fused with node-side gate payloads.
// k-split W tiles: sW = 32 KB -> 96 KB total smem -> 2 blocks/SM.
//   t=0: soSV -> D_SV = nsv ⊙ soSV   (3 x 128 per node)
//   t=1: soEV -> stored raw
//   t=2: soNS -> C_NS = nss ⊙ soNS
// Also copies [nss | nsv] into out (init fold).
// ---------------------------------------------------------------------------
#define NB 64

__global__ void __launch_bounds__(256, 2) node_mlp(
    const float4* __restrict__ nss4, const float4* __restrict__ nsv4,
    const float* __restrict__ W1, const float* __restrict__ b1,
    const float* __restrict__ W2, const float* __restrict__ b2,
    float4* __restrict__ out)
{
    extern __shared__ float sm[];
    float* sW = sm;              // 64 x 128 = 8192 floats (k-half tile)
    float* sX = sm + 8192;       // 8192  (node scalars; reused in t=2 epi)
    float* sH = sX + 8192;       // 8192

    const int tid = threadIdx.x;
    const int n0 = blockIdx.x * NB;

    // init-out fold
    {
        const float4* nssb = nss4 + (size_t)n0 * 32;
        float4* outS = out + (size_t)n0 * 32;
        for (int i = tid; i < NB * 32; i += 256)
            if (n0 + (i >> 5) < NNODES) outS[i] = nssb[i];
        const float4* nsvb = nsv4 + (size_t)n0 * 96;
        float4* outV = out + (size_t)NNODES * 32 + (size_t)n0 * 96;
        for (int i = tid; i < NB * 96; i += 256)
            if (n0 + i / 96 < NNODES) outV[i] = nsvb[i];
    }

    for (int i = tid; i < NB * 32; i += 256) {
        int n = n0 + (i >> 5);
        ((float4*)sX)[i] = (n < NNODES) ? nss4[(size_t)n * 32 + (i & 31)]
                                        : make_float4(0.f, 0.f, 0.f, 0.f);
    }
    __syncthreads();

    const int tx = tid & 31, ty = tid >> 5;
    const int c0 = tx * 4;

    u64 acc[8][2];

    // ---- phase 1: H = silu(X @ W1 + b1), two k-halves ----
    #pragma unroll
    for (int i = 0; i < 8; i++) { acc[i][0] = 0ull; acc[i][1] = 0ull; }
    for (int h = 0; h < 2; h++) {
        for (int i = tid; i < 2048; i += 256)
            ((float4*)sW)[i] = ((const float4*)W1)[h * 2048 + i];
        __syncthreads();
        #pragma unroll 4
        for (int k = 0; k < 64; k += 4) {
            const ulonglong2 w0 = *(const ulonglong2*)&sW[(k + 0) * 128 + c0];
            const ulonglong2 w1 = *(const ulonglong2*)&sW[(k + 1) * 128 + c0];
            const ulonglong2 w2 = *(const ulonglong2*)&sW[(k + 2) * 128 + c0];
            const ulonglong2 w3 = *(const ulonglong2*)&sW[(k + 3) * 128 + c0];
            #pragma unroll
            for (int i = 0; i < 8; i++) {
                const float4 xv = *(const float4*)&sX[(ty * 8 + i) * 128 + h * 64 + k];
                const u64 x0 = pack2(xv.x), x1 = pack2(xv.y);
                const u64 x2 = pack2(xv.z), x3 = pack2(xv.w);
                fma2(acc[i][0], x0, w0.x); fma2(acc[i][1], x0, w0.y);
                fma2(acc[i][0], x1, w1.x); fma2(acc[i][1], x1, w1.y);
                fma2(acc[i][0], x2, w2.x); fma2(acc[i][1], x2, w2.y);
                fma2(acc[i][0], x3, w3.x); fma2(acc[i][1], x3, w3.y);
            }
        }
        __syncthreads();
    }
    {
        const float4 bb = __ldg((const float4*)&b1[c0]);
        #pragma unroll
        for (int i = 0; i < 8; i++) {
            const float2 lo = unpack2(acc[i][0]);
            const float2 hi = unpack2(acc[i][1]);
            float4 h = make_float4(lo.x + bb.x, lo.y + bb.y, hi.x + bb.z, hi.y + bb.w);
            h.x = h.x / (1.f + __expf(-h.x));
            h.y = h.y / (1.f + __expf(-h.y));
            h.z = h.z / (1.f + __expf(-h.z));
            h.w = h.w / (1.f + __expf(-h.w));
            *(float4*)&sH[(ty * 8 + i) * 128 + c0] = h;
        }
    }
    __syncthreads();

    // ---- phase 2: three output tiles, two k-halves each ----
    for (int t = 0; t < 3; t++) {
        #pragma unroll
        for (int i = 0; i < 8; i++) { acc[i][0] = 0ull; acc[i][1] = 0ull; }
        for (int h = 0; h < 2; h++) {
            for (int i = tid; i < 2048; i += 256) {
                int k = i >> 5, jj = i & 31;
                ((float4*)sW)[i] =
                    *(const float4*)&W2[(size_t)(h * 64 + k) * 384 + t * 128 + jj * 4];
            }
            __syncthreads();
            #pragma unroll 4
            for (int k = 0; k < 64; k += 4) {
                const ulonglong2 w0 = *(const ulonglong2*)&sW[(k + 0) * 128 + c0];
                const ulonglong2 w1 = *(const ulonglong2*)&sW[(k + 1) * 128 + c0];
                const ulonglong2 w2 = *(const ulonglong2*)&sW[(k + 2) * 128 + c0];
                const ulonglong2 w3 = *(const ulonglong2*)&sW[(k + 3) * 128 + c0];
                #pragma unroll
                for (int i = 0; i < 8; i++) {
                    const float4 xv = *(const float4*)&sH[(ty * 8 + i) * 128 + h * 64 + k];
                    const u64 x0 = pack2(xv.x), x1 = pack2(xv.y);
                    const u64 x2 = pack2(xv.z), x3 = pack2(xv.w);
                    fma2(acc[i][0], x0, w0.x); fma2(acc[i][1], x0, w0.y);
                    fma2(acc[i][0], x1, w1.x); fma2(acc[i][1], x1, w1.y);
                    fma2(acc[i][0], x2, w2.x); fma2(acc[i][1], x2, w2.y);
                    fma2(acc[i][0], x3, w3.x); fma2(acc[i][1], x3, w3.y);
                }
            }
            __syncthreads();
        }
        const float4 bb = __ldg((const float4*)&b2[t * 128 + c0]);
        #pragma unroll
        for (int i = 0; i < 8; i++) {
            const int ln = ty * 8 + i;
            const int n = n0 + ln;
            if (n >= NNODES) continue;
            const float2 lo = unpack2(acc[i][0]);
            const float2 hi = unpack2(acc[i][1]);
            const float4 so = make_float4(lo.x + bb.x, lo.y + bb.y,
                                          hi.x + bb.z, hi.y + bb.w);
            if (t == 0) {
                #pragma unroll
                for (int d3 = 0; d3 < 3; d3++) {
                    const float4 xv =
                        __ldg((const float4*)((const float*)nsv4 +
                                              (size_t)n * 384 + d3 * 128 + c0));
                    *(float4*)&g_dsv[(size_t)n * 384 + d3 * 128 + c0] =
                        f4_mul(xv, so);
                }
            } else if (t == 1) {
                *(float4*)&g_sev[(size_t)n * 128 + c0] = so;
            } else {
                const float4 xs = *(const float4*)&sX[ln * 128 + c0];
                *(float4*)&g_cns[(size_t)n * 128 + c0] = f4_mul(xs, so);
            }
        }
    }
}

// ---------------------------------------------------------------------------
// Kernel 2: per-edge filter (f32x2, EPW=4, k-step-2 with float2 ES broadcast)
//           + fused-gate messages + RED scatter.  launch_bounds(128,5).
// ---------------------------------------------------------------------------
#define EPW 4

__global__ void __launch_bounds__(128, 5) edge_kernel(
    const float* __restrict__ edge_state, const float* __restrict__ edge_vector,
    const float* __restrict__ edge_distance, const int* __restrict__ edges,
    const float* __restrict__ Wf, const float* __restrict__ bf,
    float* __restrict__ out)
{
    __shared__ __align__(16) float sWf[ESZ * 384];
    __shared__ __align__(16) float sbf[384];
    __shared__ __align__(16) float sES[4][EPW * ESZ];

    const int tid = threadIdx.x;
    for (int i = tid; i < ESZ * 384 / 4; i += 128)
        ((float4*)sWf)[i] = ((const float4*)Wf)[i];
    for (int i = tid; i < 96; i += 128)
        ((float4*)sbf)[i] = ((const float4*)bf)[i];
    __syncthreads();

    const int lane  = tid & 31;
    const int warp  = tid >> 5;
    const int gwarp = blockIdx.x * 4 + warp;
    const int nwarp = gridDim.x * 4;
    const int c0    = lane * 4;
    float* myES = sES[warp];

    float* __restrict__ outS = out;
    float* __restrict__ outV = out + (size_t)NNODES * NSZ;

    for (int e0 = gwarp * EPW; e0 < NEDGES; e0 += nwarp * EPW) {
        // stage EPW edges' edge_state (contiguous, coalesced)
        __syncwarp();
        if (lane < EPW * 5) {
            ((float4*)myES)[lane] =
                __ldg((const float4*)&edge_state[(size_t)e0 * ESZ] + lane);
        }
        __syncwarp();

        // filter GEMM: acc = bf + es @ Wf (packed f32x2, k-step 2)
        u64 acc[EPW][6];
        {
            const ulonglong2 tS = *(const ulonglong2*)&sbf[c0];
            const ulonglong2 tE = *(const ulonglong2*)&sbf[128 + c0];
            const ulonglong2 tN = *(const ulonglong2*)&sbf[256 + c0];
            #pragma unroll
            for (int e = 0; e < EPW; e++) {
                acc[e][0] = tS.x; acc[e][1] = tS.y;
                acc[e][2] = tE.x; acc[e][3] = tE.y;
                acc[e][4] = tN.x; acc[e][5] = tN.y;
            }
        }
        #pragma unroll
        for (int k = 0; k < ESZ; k += 2) {
            const ulonglong2 wS0 = *(const ulonglong2*)&sWf[k * 384 + c0];
            const ulonglong2 wE0 = *(const ulonglong2*)&sWf[k * 384 + 128 + c0];
            const ulonglong2 wN0 = *(const ulonglong2*)&sWf[k * 384 + 256 + c0];
            const ulonglong2 wS1 = *(const ulonglong2*)&sWf[(k + 1) * 384 + c0];
            const ulonglong2 wE1 = *(const ulonglong2*)&sWf[(k + 1) * 384 + 128 + c0];
            const ulonglong2 wN1 = *(const ulonglong2*)&sWf[(k + 1) * 384 + 256 + c0];
            #pragma unroll
            for (int e = 0; e < EPW; e++) {
                const float2 es = *(const float2*)&myES[e * ESZ + k];  // bcast LDS.64
                const u64 p0 = pack2(es.x), p1 = pack2(es.y);
                fma2(acc[e][0], p0, wS0.x); fma2(acc[e][1], p0, wS0.y);
                fma2(acc[e][2], p0, wE0.x); fma2(acc[e][3], p0, wE0.y);
                fma2(acc[e][4], p0, wN0.x); fma2(acc[e][5], p0, wN0.y);
                fma2(acc[e][0], p1, wS1.x); fma2(acc[e][1], p1, wS1.y);
                fma2(acc[e][2], p1, wE1.x); fma2(acc[e][3], p1, wE1.y);
                fma2(acc[e][4], p1, wN1.x); fma2(acc[e][5], p1, wN1.y);
            }
        }

        // per-edge fused-gate messages + scatter
        #pragma unroll
        for (int e = 0; e < EPW; e++) {
            const int ed  = e0 + e;
            const int src = __ldg(&edges[2 * ed]);
            const int dst = __ldg(&edges[2 * ed + 1]);

            const float d = __ldg(&edge_distance[ed]);
            const float cu = (d < CUTF)
                ? 0.5f * (__cosf(3.14159265358979f * d * (1.0f / CUTF)) + 1.0f)
                : 0.0f;

            const float v0 = __ldg(&edge_vector[3 * ed]);
            const float v1 = __ldg(&edge_vector[3 * ed + 1]);
            const float v2 = __ldg(&edge_vector[3 * ed + 2]);
            const float nrm = sqrtf(v0 * v0 + v1 * v1 + v2 * v2);
            const float inv = 1.0f / fmaxf(nrm, 1e-12f);
            const float en0 = v0 * inv, en1 = v1 * inv, en2 = v2 * inv;

            float2 p0 = unpack2(acc[e][0]), p1 = unpack2(acc[e][1]);
            float2 p2 = unpack2(acc[e][2]), p3 = unpack2(acc[e][3]);
            float2 p4 = unpack2(acc[e][4]), p5 = unpack2(acc[e][5]);
            const float4 fSV = make_float4(p0.x*cu, p0.y*cu, p1.x*cu, p1.y*cu);
            const float4 fEV = make_float4(p2.x*cu, p2.y*cu, p3.x*cu, p3.y*cu);
            const float4 fNS = make_float4(p4.x*cu, p4.y*cu, p5.x*cu, p5.y*cu);

            // payload: 5 float4 rows (sev, cns, dsv x3)
            const float4 sev = __ldg((const float4*)&g_sev[(size_t)src * 128 + c0]);
            const float4 cns = __ldg((const float4*)&g_cns[(size_t)src * 128 + c0]);
            const float* dsv = &g_dsv[(size_t)src * 384];
            const float4 dv0 = __ldg((const float4*)&dsv[c0]);
            const float4 dv1 = __ldg((const float4*)&dsv[128 + c0]);
            const float4 dv2 = __ldg((const float4*)&dsv[256 + c0]);

            const float4 tE = f4_mul(fEV, sev);   // fwEV ⊙ soEV (hoisted)

            // scalar message
            red4(&outS[(size_t)dst * NSZ + c0], f4_mul(fNS, cns));

            // vector messages
            float* ov = &outV[(size_t)dst * 384];
            red4(&ov[c0],       f4_msg(dv0, fSV, en0, tE));
            red4(&ov[128 + c0], f4_msg(dv1, fSV, en1, tE));
            red4(&ov[256 + c0], f4_msg(dv2, fSV, en2, tE));
        }
    }
}

// ---------------------------------------------------------------------------
extern "C" void kernel_launch(void* const* d_in, const int* in_sizes, int n_in,
                              void* d_out, int out_size)
{
    const float* nss           = (const float*)d_in[0];
    const float* nsv           = (const float*)d_in[1];
    const float* edge_state    = (const float*)d_in[2];
    const float* edge_vector   = (const float*)d_in[3];
    const float* edge_distance = (const float*)d_in[4];
    const int*   edges         = (const int*)d_in[5];
    const float* W_filter      = (const float*)d_in[6];
    const float* b_filter      = (const float*)d_in[7];
    const float* W1            = (const float*)d_in[8];
    const float* b1            = (const float*)d_in[9];
    const float* W2            = (const float*)d_in[10];
    const float* b2            = (const float*)d_in[11];
    float* out = (float*)d_out;

    const int smem1 = (8192 + 8192 + 8192) * sizeof(float);   // 96 KB
    cudaFuncSetAttribute(node_mlp, cudaFuncAttributeMaxDynamicSharedMemorySize, smem1);
    node_mlp<<<(NNODES + NB - 1) / NB, 256, smem1>>>(
        (const float4*)nss, (const float4*)nsv, W1, b1, W2, b2, (float4*)out);

    edge_kernel<<<1480, 128>>>(edge_state, edge_vector, edge_distance,
                               edges, W_filter, b_filter, out);
}